// round 1
// baseline (speedup 1.0000x reference)
#include <cuda_runtime.h>
#include <cuda_bf16.h>
#include <math.h>

// ---------------- scratch (no cudaMalloc allowed) ----------------
__device__ float g_h1[4096];     // after in_W0
__device__ float g_h2[4096];     // after in_W1
__device__ float g_params[2112]; // after in_W2
__device__ float g_cpg[64];      // cpg_out
__device__ float g_h3[2048];     // after out_W0
__device__ float g_h4[2048];     // after out_W1

// ---------------- reductions ----------------
__device__ __forceinline__ float warp_reduce(float v) {
#pragma unroll
    for (int o = 16; o; o >>= 1) v += __shfl_down_sync(0xffffffffu, v, o);
    return v;
}

__device__ __forceinline__ float block_reduce_256(float v) {
    __shared__ float sm[8];
    int lane = threadIdx.x & 31, w = threadIdx.x >> 5;
    v = warp_reduce(v);
    if (lane == 0) sm[w] = v;
    __syncthreads();
    if (w == 0) {
        v = (lane < 8) ? sm[lane] : 0.0f;
        v = warp_reduce(v);
    }
    return v; // valid on thread 0
}

// ---------------- GEMV kernels ----------------
// Layer 0: rows=4096, cols=2049 (last col multiplies timestep). Odd stride -> scalar coalesced.
__global__ void gemv_in0(const float* __restrict__ W, const float* __restrict__ b,
                         const float* __restrict__ x, const float* __restrict__ t,
                         float* __restrict__ y) {
    int row = blockIdx.x;
    const float* Wr = W + (size_t)row * 2049;
    float sum = 0.0f;
#pragma unroll 4
    for (int j = threadIdx.x; j < 2048; j += 256)
        sum += Wr[j] * x[j];
    if (threadIdx.x == 0) sum += Wr[2048] * (*t);
    sum = block_reduce_256(sum);
    if (threadIdx.x == 0) y[row] = fmaxf(sum + b[row], 0.0f);
}

// Generic float4 GEMV, one block (256 thr) per row; cols % 4 == 0.
template<bool RELU>
__global__ void gemv_f4(const float* __restrict__ W, const float* __restrict__ b,
                        const float* __restrict__ x, float* __restrict__ y, int cols) {
    int row = blockIdx.x;
    const float4* Wr = (const float4*)(W + (size_t)row * cols);
    const float4* x4 = (const float4*)x;
    int n4 = cols >> 2;
    float sum = 0.0f;
#pragma unroll 4
    for (int j = threadIdx.x; j < n4; j += 256) {
        float4 w = Wr[j], v = x4[j];
        sum += w.x * v.x + w.y * v.y + w.z * v.z + w.w * v.w;
    }
    sum = block_reduce_256(sum);
    if (threadIdx.x == 0) {
        float r = sum + b[row];
        y[row] = RELU ? fmaxf(r, 0.0f) : r;
    }
}

// Small GEMV (cols = 64): one warp per row. Block = 256 thr = 8 rows.
__global__ void gemv_w64(const float* __restrict__ W, const float* __restrict__ b,
                         const float* __restrict__ x, float* __restrict__ y, int rows) {
    int row = (blockIdx.x * blockDim.x + threadIdx.x) >> 5;
    int lane = threadIdx.x & 31;
    if (row >= rows) return;
    const float* Wr = W + (size_t)row * 64;
    float sum = Wr[lane] * x[lane] + Wr[32 + lane] * x[32 + lane];
    sum = warp_reduce(sum);
    if (lane == 0) y[row] = fmaxf(sum + b[row], 0.0f);
}

// ---------------- CPG RK4(3/8) step: one warp ----------------
// Reference ODE layout (replicated exactly, including its slot permutation):
//   s0' = s1
//   s1' = ifr[i] + sum_j s0[i]*cw[i][j]*sin(s2[j]-s2[i]-pb[i][j])
//   s2' = 1000*(250*(ia[i]-s0[i]) - s1[i])
// Output: a = new[0:32], ph = new[32:64]; cpg_out = [a*cos(ph), a*sin(ph)]
__global__ void cpg_step(const float* __restrict__ params, const float* __restrict__ state,
                         const float* __restrict__ t_ptr, float* __restrict__ out_state,
                         float* __restrict__ cpg_out) {
    const int i = threadIdx.x; // 0..31
    float ia  = params[i];
    float ifr = params[32 + i];
    float cw[32], pb[32];
#pragma unroll
    for (int j = 0; j < 32; j++) {
        cw[j] = params[64 + 32 * i + j];
        pb[j] = params[64 + 1024 + 32 * i + j];
    }
    const float h = *t_ptr;
    float s0 = state[i], s1 = state[32 + i], s2 = state[64 + i];

    auto f = [&](float a0, float a1, float a2, float& d0, float& d1, float& d2) {
        d0 = a1;
        float coup = 0.0f;
#pragma unroll
        for (int j = 0; j < 32; j++) {
            float phj = __shfl_sync(0xffffffffu, a2, j);
            float arg = phj - a2 - pb[j];
            coup += a0 * cw[j] * (float)sin((double)arg); // DP sin: safe vs fast-math
        }
        d1 = ifr + coup;
        d2 = 1000.0f * (250.0f * (ia - a0) - a1);
    };

    float k10, k11, k12, k20, k21, k22, k30, k31, k32, k40, k41, k42;
    f(s0, s1, s2, k10, k11, k12);
    f(s0 + h * k10 / 3.0f, s1 + h * k11 / 3.0f, s2 + h * k12 / 3.0f, k20, k21, k22);
    f(s0 + h * (k20 - k10 / 3.0f), s1 + h * (k21 - k11 / 3.0f), s2 + h * (k22 - k12 / 3.0f),
      k30, k31, k32);
    f(s0 + h * (k10 - k20 + k30), s1 + h * (k11 - k21 + k31), s2 + h * (k12 - k22 + k32),
      k40, k41, k42);

    float n0 = s0 + h * 0.125f * (k10 + 3.0f * (k20 + k30) + k40);
    float n1 = s1 + h * 0.125f * (k11 + 3.0f * (k21 + k31) + k41);
    float n2 = s2 + h * 0.125f * (k12 + 3.0f * (k22 + k32) + k42);

    out_state[i]      = n0;
    out_state[32 + i] = n1;
    out_state[64 + i] = n2;

    // a = n0, ph = n1 (reference reads ph from slot [n:2n])
    cpg_out[i]      = n0 * (float)cos((double)n1);
    cpg_out[32 + i] = n0 * (float)sin((double)n1);
}

// ---------------- host ----------------
extern "C" void kernel_launch(void* const* d_in, const int* in_sizes, int n_in,
                              void* d_out, int out_size) {
    const float* state = (const float*)d_in[0];
    const float* x     = (const float*)d_in[1];
    const float* t     = (const float*)d_in[2];
    const float* inW0  = (const float*)d_in[3];
    const float* inb0  = (const float*)d_in[4];
    const float* inW1  = (const float*)d_in[5];
    const float* inb1  = (const float*)d_in[6];
    const float* inW2  = (const float*)d_in[7];
    const float* inb2  = (const float*)d_in[8];
    const float* outW0 = (const float*)d_in[9];
    const float* outb0 = (const float*)d_in[10];
    const float* outW1 = (const float*)d_in[11];
    const float* outb1 = (const float*)d_in[12];
    const float* outW2 = (const float*)d_in[13];
    const float* outb2 = (const float*)d_in[14];
    float* out = (float*)d_out;

    float *h1, *h2, *params, *cpg, *h3, *h4;
    cudaGetSymbolAddress((void**)&h1, g_h1);
    cudaGetSymbolAddress((void**)&h2, g_h2);
    cudaGetSymbolAddress((void**)&params, g_params);
    cudaGetSymbolAddress((void**)&cpg, g_cpg);
    cudaGetSymbolAddress((void**)&h3, g_h3);
    cudaGetSymbolAddress((void**)&h4, g_h4);

    // input MLP
    gemv_in0<<<4096, 256>>>(inW0, inb0, x, t, h1);
    gemv_f4<true><<<4096, 256>>>(inW1, inb1, h1, h2, 4096);
    gemv_f4<false><<<2112, 256>>>(inW2, inb2, h2, params, 4096);

    // CPG RK4 step: writes new_state to out[0:96], cpg_out[64]
    cpg_step<<<1, 32>>>(params, state, t, out, cpg);

    // output MLP
    gemv_w64<<<(2048 * 32 + 255) / 256, 256>>>(outW0, outb0, cpg, h3, 2048);
    gemv_f4<true><<<2048, 256>>>(outW1, outb1, h3, h4, 2048);
    gemv_f4<false><<<1024, 256>>>(outW2, outb2, h4, out + 96, 2048);
}

// round 2
// speedup vs baseline: 3.0393x; 3.0393x over previous
#include <cuda_runtime.h>
#include <cuda_bf16.h>
#include <math.h>

// ---------------- scratch (no cudaMalloc allowed) ----------------
__device__ float g_h1[4096];     // after in_W0
__device__ float g_h2[4096];     // after in_W1
__device__ float g_params[2112]; // after in_W2
__device__ float g_cpg[64];      // cpg_out
__device__ float g_h3[2048];     // after out_W0
__device__ float g_h4[2048];     // after out_W1

// ---------------- reductions ----------------
__device__ __forceinline__ float warp_reduce(float v) {
#pragma unroll
    for (int o = 16; o; o >>= 1) v += __shfl_down_sync(0xffffffffu, v, o);
    return v;
}

__device__ __forceinline__ float warp_reduce_bfly(float v) {
#pragma unroll
    for (int o = 16; o; o >>= 1) v += __shfl_xor_sync(0xffffffffu, v, o);
    return v; // valid on ALL lanes
}

__device__ __forceinline__ float block_reduce_256(float v) {
    __shared__ float sm[8];
    int lane = threadIdx.x & 31, w = threadIdx.x >> 5;
    v = warp_reduce(v);
    if (lane == 0) sm[w] = v;
    __syncthreads();
    if (w == 0) {
        v = (lane < 8) ? sm[lane] : 0.0f;
        v = warp_reduce(v);
    }
    return v; // valid on thread 0
}

// ---------------- accurate sin/cos: DP range reduction + SP minimax core ----
// Immune to --use_fast_math (hand-rolled). Args can reach O(1e3-1e5) because
// a_dd (~1e5) integrates into the phase slot at RK stage points; the quadrant
// index and residual are computed in double so reduction error is ~1e-13.
__device__ __forceinline__ float sin_core_d(double xd) {
    double q = rint(xd * 0.63661977236758138); // x * 2/pi
    int n = ((int)q) & 3;                      // two's complement -> correct mod 4
    float rf = (float)fma(q, -1.5707963267948966, xd); // r in [-pi/4, pi/4]
    float r2 = rf * rf;
    // sin poly
    float ps = fmaf(r2, fmaf(r2, -1.9515295891e-4f, 8.3321608736e-3f), -1.6666654611e-1f);
    float s  = fmaf(rf * r2, ps, rf);
    // cos poly
    float pc = fmaf(r2, fmaf(r2, -1.388731625493765e-3f, 4.166664568298827e-2f),
                    -4.999999905424326e-1f);
    float c  = fmaf(r2, pc, 1.0f);
    float v  = (n & 1) ? c : s;
    return (n & 2) ? -v : v;
}
__device__ __forceinline__ float fast_sin(float x) { return sin_core_d((double)x); }
__device__ __forceinline__ float fast_cos(float x) {
    return sin_core_d((double)x + 1.5707963267948966);
}

// ---------------- GEMV kernels ----------------
// Layer 0: rows=4096, cols=2049 (last col multiplies timestep).
__global__ void gemv_in0(const float* __restrict__ W, const float* __restrict__ b,
                         const float* __restrict__ x, const float* __restrict__ t,
                         float* __restrict__ y) {
    int row = blockIdx.x;
    const float* Wr = W + (size_t)row * 2049;
    float sum = 0.0f;
#pragma unroll 4
    for (int j = threadIdx.x; j < 2048; j += 256)
        sum += Wr[j] * x[j];
    if (threadIdx.x == 0) sum += Wr[2048] * (*t);
    sum = block_reduce_256(sum);
    if (threadIdx.x == 0) y[row] = fmaxf(sum + b[row], 0.0f);
}

// Generic float4 GEMV, one block (256 thr) per row; cols % 4 == 0.
template<bool RELU>
__global__ void gemv_f4(const float* __restrict__ W, const float* __restrict__ b,
                        const float* __restrict__ x, float* __restrict__ y, int cols) {
    int row = blockIdx.x;
    const float4* Wr = (const float4*)(W + (size_t)row * cols);
    const float4* x4 = (const float4*)x;
    int n4 = cols >> 2;
    float sum = 0.0f;
#pragma unroll 4
    for (int j = threadIdx.x; j < n4; j += 256) {
        float4 w = Wr[j], v = x4[j];
        sum += w.x * v.x + w.y * v.y + w.z * v.z + w.w * v.w;
    }
    sum = block_reduce_256(sum);
    if (threadIdx.x == 0) {
        float r = sum + b[row];
        y[row] = RELU ? fmaxf(r, 0.0f) : r;
    }
}

// Small GEMV (cols = 64): one warp per row.
__global__ void gemv_w64(const float* __restrict__ W, const float* __restrict__ b,
                         const float* __restrict__ x, float* __restrict__ y, int rows) {
    int row = (blockIdx.x * blockDim.x + threadIdx.x) >> 5;
    int lane = threadIdx.x & 31;
    if (row >= rows) return;
    const float* Wr = W + (size_t)row * 64;
    float sum = Wr[lane] * x[lane] + Wr[32 + lane] * x[32 + lane];
    sum = warp_reduce(sum);
    if (lane == 0) y[row] = fmaxf(sum + b[row], 0.0f);
}

// ---------------- CPG RK4(3/8) step: 1024 threads, warp=i, lane=j ----------
// Reference ODE layout (replicated exactly, including its slot permutation):
//   s0' = s1
//   s1' = ifr[i] + sum_j s0[i]*cw[i][j]*sin(s2[j]-s2[i]-pb[i][j])
//   s2' = 1000*(250*(ia[i]-s0[i]) - s1[i])
// Output: a = new[0:32], ph = new[32:64]; cpg_out = [a*cos(ph), a*sin(ph)]
__global__ void cpg_step(const float* __restrict__ params, const float* __restrict__ state,
                         const float* __restrict__ t_ptr, float* __restrict__ out_state,
                         float* __restrict__ cpg_out) {
    const int tid  = threadIdx.x;
    const int i    = tid >> 5;  // oscillator (warp)
    const int lane = tid & 31;  // coupling partner j

    __shared__ float sh_ph[32]; // phase-slot value of each oscillator at stage point

    const float cw_ij = params[64 + 32 * i + lane];
    const float pb_ij = params[64 + 1024 + 32 * i + lane];
    const float ia  = params[i];
    const float ifr = params[32 + i];
    const float h   = *t_ptr;
    const float s0 = state[i], s1 = state[32 + i], s2 = state[64 + i];

    // Stage evaluation: (a0,a1,a2) identical across lanes of warp i.
    // Returns (d0,d1,d2) identical across lanes (butterfly reduce).
    auto f = [&](float a0, float a1, float a2, float& d0, float& d1, float& d2) {
        if (lane == 0) sh_ph[i] = a2;
        __syncthreads();
        float phj = sh_ph[lane];
        __syncthreads(); // protect sh_ph before next stage overwrites
        float term = a0 * cw_ij * fast_sin(phj - a2 - pb_ij);
        d1 = ifr + warp_reduce_bfly(term);
        d0 = a1;
        d2 = 1000.0f * (250.0f * (ia - a0) - a1);
    };

    float k10, k11, k12, k20, k21, k22, k30, k31, k32, k40, k41, k42;
    f(s0, s1, s2, k10, k11, k12);
    f(s0 + h * k10 / 3.0f, s1 + h * k11 / 3.0f, s2 + h * k12 / 3.0f, k20, k21, k22);
    f(s0 + h * (k20 - k10 / 3.0f), s1 + h * (k21 - k11 / 3.0f), s2 + h * (k22 - k12 / 3.0f),
      k30, k31, k32);
    f(s0 + h * (k10 - k20 + k30), s1 + h * (k11 - k21 + k31), s2 + h * (k12 - k22 + k32),
      k40, k41, k42);

    float n0 = s0 + h * 0.125f * (k10 + 3.0f * (k20 + k30) + k40);
    float n1 = s1 + h * 0.125f * (k11 + 3.0f * (k21 + k31) + k41);
    float n2 = s2 + h * 0.125f * (k12 + 3.0f * (k22 + k32) + k42);

    if (lane == 0) {
        out_state[i]      = n0;
        out_state[32 + i] = n1;
        out_state[64 + i] = n2;
        // a = n0, ph = n1 (reference reads ph from slot [n:2n])
        cpg_out[i]      = n0 * fast_cos(n1);
        cpg_out[32 + i] = n0 * fast_sin(n1);
    }
}

// ---------------- host ----------------
extern "C" void kernel_launch(void* const* d_in, const int* in_sizes, int n_in,
                              void* d_out, int out_size) {
    const float* state = (const float*)d_in[0];
    const float* x     = (const float*)d_in[1];
    const float* t     = (const float*)d_in[2];
    const float* inW0  = (const float*)d_in[3];
    const float* inb0  = (const float*)d_in[4];
    const float* inW1  = (const float*)d_in[5];
    const float* inb1  = (const float*)d_in[6];
    const float* inW2  = (const float*)d_in[7];
    const float* inb2  = (const float*)d_in[8];
    const float* outW0 = (const float*)d_in[9];
    const float* outb0 = (const float*)d_in[10];
    const float* outW1 = (const float*)d_in[11];
    const float* outb1 = (const float*)d_in[12];
    const float* outW2 = (const float*)d_in[13];
    const float* outb2 = (const float*)d_in[14];
    float* out = (float*)d_out;

    float *h1, *h2, *params, *cpg, *h3, *h4;
    cudaGetSymbolAddress((void**)&h1, g_h1);
    cudaGetSymbolAddress((void**)&h2, g_h2);
    cudaGetSymbolAddress((void**)&params, g_params);
    cudaGetSymbolAddress((void**)&cpg, g_cpg);
    cudaGetSymbolAddress((void**)&h3, g_h3);
    cudaGetSymbolAddress((void**)&h4, g_h4);

    // input MLP
    gemv_in0<<<4096, 256>>>(inW0, inb0, x, t, h1);
    gemv_f4<true><<<4096, 256>>>(inW1, inb1, h1, h2, 4096);
    gemv_f4<false><<<2112, 256>>>(inW2, inb2, h2, params, 4096);

    // CPG RK4 step: writes new_state to out[0:96], cpg_out[64]
    cpg_step<<<1, 1024>>>(params, state, t, out, cpg);

    // output MLP
    gemv_w64<<<(2048 * 32 + 255) / 256, 256>>>(outW0, outb0, cpg, h3, 2048);
    gemv_f4<true><<<2048, 256>>>(outW1, outb1, h3, h4, 2048);
    gemv_f4<false><<<1024, 256>>>(outW2, outb2, h4, out + 96, 2048);
}

// round 3
// speedup vs baseline: 3.6988x; 1.2170x over previous
#include <cuda_runtime.h>
#include <cuda_bf16.h>
#include <math.h>

// ---------------- scratch (no cudaMalloc allowed) ----------------
__device__ __align__(16) float g_h1[4096];     // after in_W0
__device__ __align__(16) float g_h2[4096];     // after in_W1
__device__ __align__(16) float g_params[2112]; // after in_W2
__device__ __align__(16) float g_cpg[64];      // cpg_out
__device__ __align__(16) float g_h3[2048];     // after out_W0
__device__ __align__(16) float g_h4[2048];     // after out_W1

// ---------------- reductions ----------------
__device__ __forceinline__ float warp_reduce(float v) {
#pragma unroll
    for (int o = 16; o; o >>= 1) v += __shfl_down_sync(0xffffffffu, v, o);
    return v;
}

// ---------------- accurate sin: fp32 Cody-Waite 3-term + quadrant ----------
// Immune to --use_fast_math (hand-rolled). fma-based reduction: each step has a
// single rounding at the (shrinking) result magnitude, so total abs error is
// ~2e-7 rad for |x| up to ~3e4. DP fallback for larger args (never hit here).
// qoff rotates the quadrant: qoff=1 gives cos.
__device__ __forceinline__ float trig_acc(float x, int qoff) {
    float q, r;
    if (__builtin_expect(fabsf(x) > 32768.0f, 0)) {
        double xd = (double)x;
        double qd = rint(xd * 0.63661977236758138);
        q = (float)qd;
        r = (float)fma(qd, -1.5707963267948966, xd);
    } else {
        q = rintf(x * 0.63661977236758138f);
        r = fmaf(q, -1.5703125f, x);
        r = fmaf(q, -4.837512969970703125e-4f, r);
        r = fmaf(q, -7.549789948768648e-8f, r);
    }
    int n = ((int)q + qoff) & 3;
    float r2 = r * r;
    float ps = fmaf(r2, fmaf(r2, -1.9515295891e-4f, 8.3321608736e-3f), -1.6666654611e-1f);
    float s  = fmaf(r * r2, ps, r);
    float pc = fmaf(r2, fmaf(r2, -1.388731625493765e-3f, 4.166664568298827e-2f),
                    -4.999999905424326e-1f);
    float c  = fmaf(r2, pc, 1.0f);
    float v  = (n & 1) ? c : s;
    return (n & 2) ? -v : v;
}
__device__ __forceinline__ float sin_acc(float x) { return trig_acc(x, 0); }
__device__ __forceinline__ float cos_acc(float x) { return trig_acc(x, 1); }

// ---------------- GEMV kernels (2 rows per block) ----------------
// Layer 0: rows=4096, cols=2049 (last col multiplies timestep). Scalar loads.
__global__ void gemv_in0(const float* __restrict__ W, const float* __restrict__ b,
                         const float* __restrict__ x, const float* __restrict__ t,
                         float* __restrict__ y) {
    int r0 = blockIdx.x * 2;
    const float* W0 = W + (size_t)r0 * 2049;
    const float* W1 = W0 + 2049;
    float s0 = 0.0f, s1 = 0.0f;
#pragma unroll
    for (int it = 0; it < 8; it++) {
        int j = threadIdx.x + it * 256;
        float xv = x[j];
        s0 = fmaf(W0[j], xv, s0);
        s1 = fmaf(W1[j], xv, s1);
    }
    if (threadIdx.x == 0) {
        float tv = *t;
        s0 = fmaf(W0[2048], tv, s0);
        s1 = fmaf(W1[2048], tv, s1);
    }
    __shared__ float sm0[8], sm1[8];
    int lane = threadIdx.x & 31, w = threadIdx.x >> 5;
    s0 = warp_reduce(s0); s1 = warp_reduce(s1);
    if (lane == 0) { sm0[w] = s0; sm1[w] = s1; }
    __syncthreads();
    if (w == 0) {
        s0 = (lane < 8) ? sm0[lane] : 0.0f; s0 = warp_reduce(s0);
        s1 = (lane < 8) ? sm1[lane] : 0.0f; s1 = warp_reduce(s1);
        if (lane == 0) {
            y[r0]     = fmaxf(s0 + b[r0], 0.0f);
            y[r0 + 1] = fmaxf(s1 + b[r0 + 1], 0.0f);
        }
    }
}

// float4 GEMV, 2 rows per 256-thread block, COLS % 1024 == 0.
template<int COLS, bool RELU>
__global__ void gemv2(const float* __restrict__ W, const float* __restrict__ b,
                      const float* __restrict__ x, float* __restrict__ y) {
    constexpr int N4 = COLS / 4;
    constexpr int ITERS = N4 / 256;
    int r0 = blockIdx.x * 2;
    const float4* W0 = (const float4*)(W + (size_t)r0 * COLS);
    const float4* W1 = (const float4*)(W + (size_t)(r0 + 1) * COLS);
    const float4* x4 = (const float4*)x;
    float s0 = 0.0f, s1 = 0.0f;
#pragma unroll
    for (int it = 0; it < ITERS; it++) {
        int j = threadIdx.x + it * 256;
        float4 v = x4[j];
        float4 w0 = W0[j];
        float4 w1 = W1[j];
        s0 += w0.x * v.x + w0.y * v.y + w0.z * v.z + w0.w * v.w;
        s1 += w1.x * v.x + w1.y * v.y + w1.z * v.z + w1.w * v.w;
    }
    __shared__ float sm0[8], sm1[8];
    int lane = threadIdx.x & 31, w = threadIdx.x >> 5;
    s0 = warp_reduce(s0); s1 = warp_reduce(s1);
    if (lane == 0) { sm0[w] = s0; sm1[w] = s1; }
    __syncthreads();
    if (w == 0) {
        s0 = (lane < 8) ? sm0[lane] : 0.0f; s0 = warp_reduce(s0);
        s1 = (lane < 8) ? sm1[lane] : 0.0f; s1 = warp_reduce(s1);
        if (lane == 0) {
            float a = s0 + b[r0], c = s1 + b[r0 + 1];
            y[r0]     = RELU ? fmaxf(a, 0.0f) : a;
            y[r0 + 1] = RELU ? fmaxf(c, 0.0f) : c;
        }
    }
}

// Small GEMV (cols = 64): one warp per row.
__global__ void gemv_w64(const float* __restrict__ W, const float* __restrict__ b,
                         const float* __restrict__ x, float* __restrict__ y, int rows) {
    int row = (blockIdx.x * blockDim.x + threadIdx.x) >> 5;
    int lane = threadIdx.x & 31;
    if (row >= rows) return;
    const float* Wr = W + (size_t)row * 64;
    float sum = fmaf(Wr[lane], x[lane], Wr[32 + lane] * x[32 + lane]);
    sum = warp_reduce(sum);
    if (lane == 0) y[row] = fmaxf(sum + b[row], 0.0f);
}

// ---------------- CPG RK4(3/8) step: 128 threads ----------------
// thread t: oscillator i = t&31 (replicated over 4 groups g = t>>5, each group
// handles 8 coupling partners j in [8g, 8g+8)).
// ODE (reference slot permutation replicated exactly):
//   s0' = s1
//   s1' = ifr[i] + sum_j s0[i]*cw[i][j]*sin(s2[j]-s2[i]-pb[i][j])
//   s2' = 1000*(250*(ia[i]-s0[i]) - s1[i])
// Output: a = new[0:32], ph = new[32:64]; cpg_out = [a*cos(ph), a*sin(ph)]
__global__ void cpg_step(const float* __restrict__ params, const float* __restrict__ state,
                         const float* __restrict__ t_ptr, float* __restrict__ out_state,
                         float* __restrict__ cpg_out) {
    const int tid = threadIdx.x;  // 0..127
    const int i   = tid & 31;
    const int g   = tid >> 5;

    __shared__ float sh_ph[2][32];   // double-buffered stage-point phases
    __shared__ float sh_part[4][32]; // per-group partial coupling sums

    // cw/pb slices: params + 64 + 32*i + 8*g is a multiple of 8 floats -> 32B aligned
    float4 cwa = ((const float4*)(params + 64 + 32 * i + 8 * g))[0];
    float4 cwb = ((const float4*)(params + 64 + 32 * i + 8 * g))[1];
    float4 pba = ((const float4*)(params + 64 + 1024 + 32 * i + 8 * g))[0];
    float4 pbb = ((const float4*)(params + 64 + 1024 + 32 * i + 8 * g))[1];
    float cw8[8] = {cwa.x, cwa.y, cwa.z, cwa.w, cwb.x, cwb.y, cwb.z, cwb.w};
    float pb8[8] = {pba.x, pba.y, pba.z, pba.w, pbb.x, pbb.y, pbb.z, pbb.w};

    const float ia  = params[i];
    const float ifr = params[32 + i];
    const float h   = *t_ptr;
    const float s0 = state[i], s1 = state[32 + i], s2 = state[64 + i];

    int stage = 0;
    auto f = [&](float a0, float a1, float a2, float& d0, float& d1, float& d2) {
        int buf = stage & 1;
        if (g == 0) sh_ph[buf][i] = a2;
        __syncthreads();
        const float* ph = sh_ph[buf] + 8 * g;
        float acc0 = 0.0f, acc1 = 0.0f;
#pragma unroll
        for (int k = 0; k < 8; k += 2) {
            acc0 = fmaf(cw8[k],     sin_acc(ph[k]     - a2 - pb8[k]),     acc0);
            acc1 = fmaf(cw8[k + 1], sin_acc(ph[k + 1] - a2 - pb8[k + 1]), acc1);
        }
        sh_part[g][i] = acc0 + acc1;
        __syncthreads();
        float coup = (sh_part[0][i] + sh_part[1][i]) + (sh_part[2][i] + sh_part[3][i]);
        d1 = fmaf(a0, coup, ifr);
        d0 = a1;
        d2 = 1000.0f * fmaf(250.0f, ia - a0, -a1);
        stage++;
    };

    float k10, k11, k12, k20, k21, k22, k30, k31, k32, k40, k41, k42;
    f(s0, s1, s2, k10, k11, k12);
    f(s0 + h * k10 / 3.0f, s1 + h * k11 / 3.0f, s2 + h * k12 / 3.0f, k20, k21, k22);
    f(s0 + h * (k20 - k10 / 3.0f), s1 + h * (k21 - k11 / 3.0f), s2 + h * (k22 - k12 / 3.0f),
      k30, k31, k32);
    f(s0 + h * (k10 - k20 + k30), s1 + h * (k11 - k21 + k31), s2 + h * (k12 - k22 + k32),
      k40, k41, k42);

    float n0 = s0 + h * 0.125f * (k10 + 3.0f * (k20 + k30) + k40);
    float n1 = s1 + h * 0.125f * (k11 + 3.0f * (k21 + k31) + k41);
    float n2 = s2 + h * 0.125f * (k12 + 3.0f * (k22 + k32) + k42);

    if (g == 0) {
        out_state[i]      = n0;
        out_state[32 + i] = n1;
        out_state[64 + i] = n2;
        // a = n0, ph = n1 (reference reads ph from slot [n:2n])
        cpg_out[i]      = n0 * cos_acc(n1);
        cpg_out[32 + i] = n0 * sin_acc(n1);
    }
}

// ---------------- host ----------------
extern "C" void kernel_launch(void* const* d_in, const int* in_sizes, int n_in,
                              void* d_out, int out_size) {
    const float* state = (const float*)d_in[0];
    const float* x     = (const float*)d_in[1];
    const float* t     = (const float*)d_in[2];
    const float* inW0  = (const float*)d_in[3];
    const float* inb0  = (const float*)d_in[4];
    const float* inW1  = (const float*)d_in[5];
    const float* inb1  = (const float*)d_in[6];
    const float* inW2  = (const float*)d_in[7];
    const float* inb2  = (const float*)d_in[8];
    const float* outW0 = (const float*)d_in[9];
    const float* outb0 = (const float*)d_in[10];
    const float* outW1 = (const float*)d_in[11];
    const float* outb1 = (const float*)d_in[12];
    const float* outW2 = (const float*)d_in[13];
    const float* outb2 = (const float*)d_in[14];
    float* out = (float*)d_out;

    float *h1, *h2, *params, *cpg, *h3, *h4;
    cudaGetSymbolAddress((void**)&h1, g_h1);
    cudaGetSymbolAddress((void**)&h2, g_h2);
    cudaGetSymbolAddress((void**)&params, g_params);
    cudaGetSymbolAddress((void**)&cpg, g_cpg);
    cudaGetSymbolAddress((void**)&h3, g_h3);
    cudaGetSymbolAddress((void**)&h4, g_h4);

    // input MLP
    gemv_in0<<<2048, 256>>>(inW0, inb0, x, t, h1);
    gemv2<4096, true><<<2048, 256>>>(inW1, inb1, h1, h2);
    gemv2<4096, false><<<1056, 256>>>(inW2, inb2, h2, params);

    // CPG RK4 step: writes new_state to out[0:96], cpg_out[64]
    cpg_step<<<1, 128>>>(params, state, t, out, cpg);

    // output MLP
    gemv_w64<<<256, 256>>>(outW0, outb0, cpg, h3, 2048);
    gemv2<2048, true><<<1024, 256>>>(outW1, outb1, h3, h4);
    gemv2<2048, false><<<512, 256>>>(outW2, outb2, h4, out + 96);
}

// round 4
// speedup vs baseline: 4.2708x; 1.1547x over previous
#include <cuda_runtime.h>
#include <cuda_bf16.h>
#include <math.h>

// ---------------- scratch (no cudaMalloc allowed) ----------------
__device__ __align__(16) float g_h1[4096];     // after in_W0
__device__ __align__(16) float g_h2[4096];     // after in_W1
__device__ __align__(16) float g_params[2112]; // after in_W2
__device__ __align__(16) float g_cpg[64];      // cpg_out
__device__ __align__(16) float g_h3[2048];     // after out_W0
__device__ __align__(16) float g_h4[2048];     // after out_W1

// ---------------- reductions ----------------
__device__ __forceinline__ float warp_reduce(float v) {
#pragma unroll
    for (int o = 16; o; o >>= 1) v += __shfl_down_sync(0xffffffffu, v, o);
    return v;
}

// ---------------- accurate sin: fp32 Cody-Waite 3-term + quadrant ----------
// Immune to --use_fast_math (hand-rolled). DP fallback for |x|>32768 (unused
// in practice). qoff=1 gives cos.
__device__ __forceinline__ float trig_acc(float x, int qoff) {
    float q, r;
    if (__builtin_expect(fabsf(x) > 32768.0f, 0)) {
        double xd = (double)x;
        double qd = rint(xd * 0.63661977236758138);
        q = (float)qd;
        r = (float)fma(qd, -1.5707963267948966, xd);
    } else {
        q = rintf(x * 0.63661977236758138f);
        r = fmaf(q, -1.5703125f, x);
        r = fmaf(q, -4.837512969970703125e-4f, r);
        r = fmaf(q, -7.549789948768648e-8f, r);
    }
    int n = ((int)q + qoff) & 3;
    float r2 = r * r;
    float ps = fmaf(r2, fmaf(r2, -1.9515295891e-4f, 8.3321608736e-3f), -1.6666654611e-1f);
    float s  = fmaf(r * r2, ps, r);
    float pc = fmaf(r2, fmaf(r2, -1.388731625493765e-3f, 4.166664568298827e-2f),
                    -4.999999905424326e-1f);
    float c  = fmaf(r2, pc, 1.0f);
    float v  = (n & 1) ? c : s;
    return (n & 2) ? -v : v;
}
__device__ __forceinline__ float sin_acc(float x) { return trig_acc(x, 0); }
__device__ __forceinline__ float cos_acc(float x) { return trig_acc(x, 1); }

// ---------------- GEMV kernels ----------------
// Layer 0: rows=4096, cols=2049 (last col multiplies timestep). Scalar loads
// (row stride 2049 breaks float4 alignment on odd rows); 2 rows/block.
__global__ void gemv_in0(const float* __restrict__ W, const float* __restrict__ b,
                         const float* __restrict__ x, const float* __restrict__ t,
                         float* __restrict__ y) {
    int r0 = blockIdx.x * 2;
    const float* W0 = W + (size_t)r0 * 2049;
    const float* W1 = W0 + 2049;
    float s0 = 0.0f, s1 = 0.0f;
#pragma unroll
    for (int it = 0; it < 8; it++) {
        int j = threadIdx.x + it * 256;
        float xv = x[j];
        s0 = fmaf(__ldcs(W0 + j), xv, s0);
        s1 = fmaf(__ldcs(W1 + j), xv, s1);
    }
    if (threadIdx.x == 0) {
        float tv = *t;
        s0 = fmaf(__ldcs(W0 + 2048), tv, s0);
        s1 = fmaf(__ldcs(W1 + 2048), tv, s1);
    }
    __shared__ float sm0[8], sm1[8];
    int lane = threadIdx.x & 31, w = threadIdx.x >> 5;
    s0 = warp_reduce(s0); s1 = warp_reduce(s1);
    if (lane == 0) { sm0[w] = s0; sm1[w] = s1; }
    __syncthreads();
    if (w == 0) {
        s0 = (lane < 8) ? sm0[lane] : 0.0f; s0 = warp_reduce(s0);
        s1 = (lane < 8) ? sm1[lane] : 0.0f; s1 = warp_reduce(s1);
        if (lane == 0) {
            y[r0]     = fmaxf(s0 + b[r0], 0.0f);
            y[r0 + 1] = fmaxf(s1 + b[r0 + 1], 0.0f);
        }
    }
}

// float4 GEMV, 4 rows per 256-thread block, COLS % 1024 == 0.
template<int COLS, bool RELU>
__global__ void gemv4(const float* __restrict__ W, const float* __restrict__ b,
                      const float* __restrict__ x, float* __restrict__ y) {
    constexpr int N4 = COLS / 4;
    constexpr int ITERS = N4 / 256;
    int r0 = blockIdx.x * 4;
    const float4* W0 = (const float4*)(W + (size_t)r0 * COLS);
    const float4* W1 = (const float4*)(W + (size_t)(r0 + 1) * COLS);
    const float4* W2 = (const float4*)(W + (size_t)(r0 + 2) * COLS);
    const float4* W3 = (const float4*)(W + (size_t)(r0 + 3) * COLS);
    const float4* x4 = (const float4*)x;
    float s0 = 0.0f, s1 = 0.0f, s2 = 0.0f, s3 = 0.0f;
#pragma unroll
    for (int it = 0; it < ITERS; it++) {
        int j = threadIdx.x + it * 256;
        float4 v  = x4[j];
        float4 w0 = __ldcs(W0 + j);
        float4 w1 = __ldcs(W1 + j);
        float4 w2 = __ldcs(W2 + j);
        float4 w3 = __ldcs(W3 + j);
        s0 += w0.x * v.x + w0.y * v.y + w0.z * v.z + w0.w * v.w;
        s1 += w1.x * v.x + w1.y * v.y + w1.z * v.z + w1.w * v.w;
        s2 += w2.x * v.x + w2.y * v.y + w2.z * v.z + w2.w * v.w;
        s3 += w3.x * v.x + w3.y * v.y + w3.z * v.z + w3.w * v.w;
    }
    __shared__ float sm[4][8];
    int lane = threadIdx.x & 31, w = threadIdx.x >> 5;
    s0 = warp_reduce(s0); s1 = warp_reduce(s1);
    s2 = warp_reduce(s2); s3 = warp_reduce(s3);
    if (lane == 0) { sm[0][w] = s0; sm[1][w] = s1; sm[2][w] = s2; sm[3][w] = s3; }
    __syncthreads();
    // warp 0 reduces all 4 rows: lanes 0-7 row0, 8-15 row1, 16-23 row2, 24-31 row3
    if (w == 0) {
        int rr = lane >> 3, sl = lane & 7;
        float v = sm[rr][sl];
        v += __shfl_down_sync(0xffffffffu, v, 4);
        v += __shfl_down_sync(0xffffffffu, v, 2);
        v += __shfl_down_sync(0xffffffffu, v, 1);
        if (sl == 0) {
            float r = v + b[r0 + rr];
            y[r0 + rr] = RELU ? fmaxf(r, 0.0f) : r;
        }
    }
}

// Small GEMV (cols = 64): one warp per row.
__global__ void gemv_w64(const float* __restrict__ W, const float* __restrict__ b,
                         const float* __restrict__ x, float* __restrict__ y, int rows) {
    int row = (blockIdx.x * blockDim.x + threadIdx.x) >> 5;
    int lane = threadIdx.x & 31;
    if (row >= rows) return;
    const float* Wr = W + (size_t)row * 64;
    float sum = fmaf(Wr[lane], x[lane], Wr[32 + lane] * x[32 + lane]);
    sum = warp_reduce(sum);
    if (lane == 0) y[row] = fmaxf(sum + b[row], 0.0f);
}

// ---------------- CPG RK4(3/8) step ----------------
// Launched with grid=148 to dodge the sm_103a low-grid issue throttle; only
// block 0 does work. 256 threads: i = tid&31 (oscillator), g = tid>>5 (8
// groups, 4 coupling partners each).
// ODE (reference slot permutation replicated exactly):
//   s0' = s1
//   s1' = ifr[i] + sum_j s0[i]*cw[i][j]*sin(s2[j]-s2[i]-pb[i][j])
//   s2' = 1000*(250*(ia[i]-s0[i]) - s1[i])
// Output: a = new[0:32], ph = new[32:64]; cpg_out = [a*cos(ph), a*sin(ph)]
__global__ void cpg_step(const float* __restrict__ params, const float* __restrict__ state,
                         const float* __restrict__ t_ptr, float* __restrict__ out_state,
                         float* __restrict__ cpg_out) {
    if (blockIdx.x != 0) return;
    const int tid = threadIdx.x;  // 0..255
    const int i   = tid & 31;
    const int g   = tid >> 5;     // 0..7

    __shared__ float sh_ph[2][32];   // double-buffered stage-point phases
    __shared__ float sh_part[8][32]; // per-group partial coupling sums

    // 4 coupling coefficients per thread; base offset multiple of 4 -> 16B aligned
    float4 cw4 = *(const float4*)(params + 64 + 32 * i + 4 * g);
    float4 pb4 = *(const float4*)(params + 64 + 1024 + 32 * i + 4 * g);
    float cwv[4] = {cw4.x, cw4.y, cw4.z, cw4.w};
    float pbv[4] = {pb4.x, pb4.y, pb4.z, pb4.w};

    const float ia  = params[i];
    const float ifr = params[32 + i];
    const float h   = *t_ptr;
    const float s0 = state[i], s1 = state[32 + i], s2 = state[64 + i];

    int stage = 0;
    auto f = [&](float a0, float a1, float a2, float& d0, float& d1, float& d2) {
        int buf = stage & 1;
        if (g == 0) sh_ph[buf][i] = a2;
        __syncthreads();
        const float* ph = sh_ph[buf] + 4 * g;
        float acc0, acc1;
        acc0 = cwv[0] * sin_acc(ph[0] - a2 - pbv[0]);
        acc1 = cwv[1] * sin_acc(ph[1] - a2 - pbv[1]);
        acc0 = fmaf(cwv[2], sin_acc(ph[2] - a2 - pbv[2]), acc0);
        acc1 = fmaf(cwv[3], sin_acc(ph[3] - a2 - pbv[3]), acc1);
        sh_part[g][i] = acc0 + acc1;
        __syncthreads();
        float coup = ((sh_part[0][i] + sh_part[1][i]) + (sh_part[2][i] + sh_part[3][i]))
                   + ((sh_part[4][i] + sh_part[5][i]) + (sh_part[6][i] + sh_part[7][i]));
        d1 = fmaf(a0, coup, ifr);
        d0 = a1;
        d2 = 1000.0f * fmaf(250.0f, ia - a0, -a1);
        stage++;
    };

    float k10, k11, k12, k20, k21, k22, k30, k31, k32, k40, k41, k42;
    f(s0, s1, s2, k10, k11, k12);
    f(s0 + h * k10 / 3.0f, s1 + h * k11 / 3.0f, s2 + h * k12 / 3.0f, k20, k21, k22);
    f(s0 + h * (k20 - k10 / 3.0f), s1 + h * (k21 - k11 / 3.0f), s2 + h * (k22 - k12 / 3.0f),
      k30, k31, k32);
    f(s0 + h * (k10 - k20 + k30), s1 + h * (k11 - k21 + k31), s2 + h * (k12 - k22 + k32),
      k40, k41, k42);

    float n0 = s0 + h * 0.125f * (k10 + 3.0f * (k20 + k30) + k40);
    float n1 = s1 + h * 0.125f * (k11 + 3.0f * (k21 + k31) + k41);
    float n2 = s2 + h * 0.125f * (k12 + 3.0f * (k22 + k32) + k42);

    if (g == 0) {
        out_state[i]      = n0;
        out_state[32 + i] = n1;
        out_state[64 + i] = n2;
        // a = n0, ph = n1 (reference reads ph from slot [n:2n])
        cpg_out[i]      = n0 * cos_acc(n1);
        cpg_out[32 + i] = n0 * sin_acc(n1);
    }
}

// ---------------- host ----------------
extern "C" void kernel_launch(void* const* d_in, const int* in_sizes, int n_in,
                              void* d_out, int out_size) {
    const float* state = (const float*)d_in[0];
    const float* x     = (const float*)d_in[1];
    const float* t     = (const float*)d_in[2];
    const float* inW0  = (const float*)d_in[3];
    const float* inb0  = (const float*)d_in[4];
    const float* inW1  = (const float*)d_in[5];
    const float* inb1  = (const float*)d_in[6];
    const float* inW2  = (const float*)d_in[7];
    const float* inb2  = (const float*)d_in[8];
    const float* outW0 = (const float*)d_in[9];
    const float* outb0 = (const float*)d_in[10];
    const float* outW1 = (const float*)d_in[11];
    const float* outb1 = (const float*)d_in[12];
    const float* outW2 = (const float*)d_in[13];
    const float* outb2 = (const float*)d_in[14];
    float* out = (float*)d_out;

    float *h1, *h2, *params, *cpg, *h3, *h4;
    cudaGetSymbolAddress((void**)&h1, g_h1);
    cudaGetSymbolAddress((void**)&h2, g_h2);
    cudaGetSymbolAddress((void**)&params, g_params);
    cudaGetSymbolAddress((void**)&cpg, g_cpg);
    cudaGetSymbolAddress((void**)&h3, g_h3);
    cudaGetSymbolAddress((void**)&h4, g_h4);

    // input MLP
    gemv_in0<<<2048, 256>>>(inW0, inb0, x, t, h1);
    gemv4<4096, true><<<1024, 256>>>(inW1, inb1, h1, h2);
    gemv4<4096, false><<<528, 256>>>(inW2, inb2, h2, params);

    // CPG RK4 step: writes new_state to out[0:96], cpg_out[64]
    cpg_step<<<148, 256>>>(params, state, t, out, cpg);

    // output MLP
    gemv_w64<<<256, 256>>>(outW0, outb0, cpg, h3, 2048);
    gemv4<2048, true><<<512, 256>>>(outW1, outb1, h3, h4);
    gemv4<2048, false><<<256, 256>>>(outW2, outb2, h4, out + 96);
}

// round 5
// speedup vs baseline: 4.2858x; 1.0035x over previous
#include <cuda_runtime.h>
#include <cuda_bf16.h>
#include <math.h>

// ---------------- scratch (no cudaMalloc allowed) ----------------
__device__ __align__(16) float g_h1[4096];     // after in_W0
__device__ __align__(16) float g_h2[4096];     // after in_W1
__device__ __align__(16) float g_params[2112]; // after in_W2
__device__ __align__(16) float g_cpg[64];      // cpg_out
__device__ __align__(16) float g_h3[2048];     // after out_W0
__device__ __align__(16) float g_h4[2048];     // after out_W1
__device__ unsigned g_done = 0;                // last-block counter (self-resetting)

// ---------------- reductions ----------------
__device__ __forceinline__ float warp_reduce(float v) {
#pragma unroll
    for (int o = 16; o; o >>= 1) v += __shfl_down_sync(0xffffffffu, v, o);
    return v;
}

// ---------------- accurate sin: fp32 Cody-Waite 3-term + quadrant ----------
// Immune to --use_fast_math (hand-rolled). DP fallback for |x|>32768 (unused
// in practice). qoff=1 gives cos.
__device__ __forceinline__ float trig_acc(float x, int qoff) {
    float q, r;
    if (__builtin_expect(fabsf(x) > 32768.0f, 0)) {
        double xd = (double)x;
        double qd = rint(xd * 0.63661977236758138);
        q = (float)qd;
        r = (float)fma(qd, -1.5707963267948966, xd);
    } else {
        q = rintf(x * 0.63661977236758138f);
        r = fmaf(q, -1.5703125f, x);
        r = fmaf(q, -4.837512969970703125e-4f, r);
        r = fmaf(q, -7.549789948768648e-8f, r);
    }
    int n = ((int)q + qoff) & 3;
    float r2 = r * r;
    float ps = fmaf(r2, fmaf(r2, -1.9515295891e-4f, 8.3321608736e-3f), -1.6666654611e-1f);
    float s  = fmaf(r * r2, ps, r);
    float pc = fmaf(r2, fmaf(r2, -1.388731625493765e-3f, 4.166664568298827e-2f),
                    -4.999999905424326e-1f);
    float c  = fmaf(r2, pc, 1.0f);
    float v  = (n & 1) ? c : s;
    return (n & 2) ? -v : v;
}
__device__ __forceinline__ float sin_acc(float x) { return trig_acc(x, 0); }
__device__ __forceinline__ float cos_acc(float x) { return trig_acc(x, 1); }

// ---------------- CPG RK4(3/8) device function (256 threads) ----------------
// i = tid&31 (oscillator), g = tid>>5 (8 groups x 4 coupling partners).
// ODE (reference slot permutation replicated exactly):
//   s0' = s1
//   s1' = ifr[i] + sum_j s0[i]*cw[i][j]*sin(s2[j]-s2[i]-pb[i][j])
//   s2' = 1000*(250*(ia[i]-s0[i]) - s1[i])
// Output: a = new[0:32], ph = new[32:64]; cpg_out = [a*cos(ph), a*sin(ph)]
// params read with __ldcg: written by OTHER blocks of this kernel (L2-coherent).
__device__ void cpg_compute(const float* params, const float* state,
                            const float* t_ptr, float* out_state, float* cpg_out) {
    const int tid = threadIdx.x;  // 0..255
    const int i   = tid & 31;
    const int g   = tid >> 5;     // 0..7

    __shared__ float sh_ph[2][32];
    __shared__ float sh_part[8][32];

    float cwv[4], pbv[4];
#pragma unroll
    for (int k = 0; k < 4; k++) {
        cwv[k] = __ldcg(params + 64 + 32 * i + 4 * g + k);
        pbv[k] = __ldcg(params + 64 + 1024 + 32 * i + 4 * g + k);
    }
    const float ia  = __ldcg(params + i);
    const float ifr = __ldcg(params + 32 + i);
    const float h   = *t_ptr;
    const float s0 = state[i], s1 = state[32 + i], s2 = state[64 + i];

    int stage = 0;
    auto f = [&](float a0, float a1, float a2, float& d0, float& d1, float& d2) {
        int buf = stage & 1;
        if (g == 0) sh_ph[buf][i] = a2;
        __syncthreads();
        const float* ph = sh_ph[buf] + 4 * g;
        float acc0, acc1;
        acc0 = cwv[0] * sin_acc(ph[0] - a2 - pbv[0]);
        acc1 = cwv[1] * sin_acc(ph[1] - a2 - pbv[1]);
        acc0 = fmaf(cwv[2], sin_acc(ph[2] - a2 - pbv[2]), acc0);
        acc1 = fmaf(cwv[3], sin_acc(ph[3] - a2 - pbv[3]), acc1);
        sh_part[g][i] = acc0 + acc1;
        __syncthreads();
        float coup = ((sh_part[0][i] + sh_part[1][i]) + (sh_part[2][i] + sh_part[3][i]))
                   + ((sh_part[4][i] + sh_part[5][i]) + (sh_part[6][i] + sh_part[7][i]));
        d1 = fmaf(a0, coup, ifr);
        d0 = a1;
        d2 = 1000.0f * fmaf(250.0f, ia - a0, -a1);
        stage++;
    };

    float k10, k11, k12, k20, k21, k22, k30, k31, k32, k40, k41, k42;
    f(s0, s1, s2, k10, k11, k12);
    f(s0 + h * k10 / 3.0f, s1 + h * k11 / 3.0f, s2 + h * k12 / 3.0f, k20, k21, k22);
    f(s0 + h * (k20 - k10 / 3.0f), s1 + h * (k21 - k11 / 3.0f), s2 + h * (k22 - k12 / 3.0f),
      k30, k31, k32);
    f(s0 + h * (k10 - k20 + k30), s1 + h * (k11 - k21 + k31), s2 + h * (k12 - k22 + k32),
      k40, k41, k42);

    float n0 = s0 + h * 0.125f * (k10 + 3.0f * (k20 + k30) + k40);
    float n1 = s1 + h * 0.125f * (k11 + 3.0f * (k21 + k31) + k41);
    float n2 = s2 + h * 0.125f * (k12 + 3.0f * (k22 + k32) + k42);

    if (g == 0) {
        out_state[i]      = n0;
        out_state[32 + i] = n1;
        out_state[64 + i] = n2;
        // a = n0, ph = n1 (reference reads ph from slot [n:2n])
        cpg_out[i]      = n0 * cos_acc(n1);
        cpg_out[32 + i] = n0 * sin_acc(n1);
    }
}

// ---------------- GEMV kernels ----------------
// Layer 0: rows=4096, cols=2049 (last col multiplies timestep). Scalar loads
// (row stride 2049 breaks float4 alignment on odd rows); 2 rows/block.
__global__ void gemv_in0(const float* __restrict__ W, const float* __restrict__ b,
                         const float* __restrict__ x, const float* __restrict__ t,
                         float* __restrict__ y) {
    int r0 = blockIdx.x * 2;
    const float* W0 = W + (size_t)r0 * 2049;
    const float* W1 = W0 + 2049;
    float s0 = 0.0f, s1 = 0.0f;
#pragma unroll
    for (int it = 0; it < 8; it++) {
        int j = threadIdx.x + it * 256;
        float xv = x[j];
        s0 = fmaf(__ldcs(W0 + j), xv, s0);
        s1 = fmaf(__ldcs(W1 + j), xv, s1);
    }
    if (threadIdx.x == 0) {
        float tv = *t;
        s0 = fmaf(__ldcs(W0 + 2048), tv, s0);
        s1 = fmaf(__ldcs(W1 + 2048), tv, s1);
    }
    __shared__ float sm0[8], sm1[8];
    int lane = threadIdx.x & 31, w = threadIdx.x >> 5;
    s0 = warp_reduce(s0); s1 = warp_reduce(s1);
    if (lane == 0) { sm0[w] = s0; sm1[w] = s1; }
    __syncthreads();
    if (w == 0) {
        s0 = (lane < 8) ? sm0[lane] : 0.0f; s0 = warp_reduce(s0);
        s1 = (lane < 8) ? sm1[lane] : 0.0f; s1 = warp_reduce(s1);
        if (lane == 0) {
            y[r0]     = fmaxf(s0 + b[r0], 0.0f);
            y[r0 + 1] = fmaxf(s1 + b[r0 + 1], 0.0f);
        }
    }
}

// float4 GEMV, 4 rows per 256-thread block, COLS % 1024 == 0.
// FUSE_CPG: after all blocks finish, the last block runs the CPG step inline.
template<int COLS, bool RELU, bool FUSE_CPG>
__global__ void gemv4(const float* __restrict__ W, const float* __restrict__ b,
                      const float* __restrict__ x, float* __restrict__ y,
                      const float* state, const float* t,
                      float* out_state, float* cpg_out) {
    constexpr int N4 = COLS / 4;
    constexpr int ITERS = N4 / 256;
    int r0 = blockIdx.x * 4;
    const float4* W0 = (const float4*)(W + (size_t)r0 * COLS);
    const float4* W1 = (const float4*)(W + (size_t)(r0 + 1) * COLS);
    const float4* W2 = (const float4*)(W + (size_t)(r0 + 2) * COLS);
    const float4* W3 = (const float4*)(W + (size_t)(r0 + 3) * COLS);
    const float4* x4 = (const float4*)x;
    float s0 = 0.0f, s1 = 0.0f, s2 = 0.0f, s3 = 0.0f;
#pragma unroll
    for (int it = 0; it < ITERS; it++) {
        int j = threadIdx.x + it * 256;
        float4 v  = x4[j];
        float4 w0 = __ldcs(W0 + j);
        float4 w1 = __ldcs(W1 + j);
        float4 w2 = __ldcs(W2 + j);
        float4 w3 = __ldcs(W3 + j);
        s0 += w0.x * v.x + w0.y * v.y + w0.z * v.z + w0.w * v.w;
        s1 += w1.x * v.x + w1.y * v.y + w1.z * v.z + w1.w * v.w;
        s2 += w2.x * v.x + w2.y * v.y + w2.z * v.z + w2.w * v.w;
        s3 += w3.x * v.x + w3.y * v.y + w3.z * v.z + w3.w * v.w;
    }
    __shared__ float sm[4][8];
    int lane = threadIdx.x & 31, w = threadIdx.x >> 5;
    s0 = warp_reduce(s0); s1 = warp_reduce(s1);
    s2 = warp_reduce(s2); s3 = warp_reduce(s3);
    if (lane == 0) { sm[0][w] = s0; sm[1][w] = s1; sm[2][w] = s2; sm[3][w] = s3; }
    __syncthreads();
    if (w == 0) {
        int rr = lane >> 3, sl = lane & 7;
        float v = sm[rr][sl];
        v += __shfl_down_sync(0xffffffffu, v, 4);
        v += __shfl_down_sync(0xffffffffu, v, 2);
        v += __shfl_down_sync(0xffffffffu, v, 1);
        if (sl == 0) {
            float r = v + b[r0 + rr];
            y[r0 + rr] = RELU ? fmaxf(r, 0.0f) : r;
        }
    }

    if (FUSE_CPG) {
        // last-block election: writers fence, then RMW on a shared counter
        __shared__ unsigned sh_last;
        __syncthreads();
        if (threadIdx.x == 0) {
            __threadfence();
            sh_last = (atomicAdd(&g_done, 1u) == gridDim.x - 1u) ? 1u : 0u;
        }
        __syncthreads();
        if (sh_last) {
            if (threadIdx.x == 0) g_done = 0; // reset for next graph replay
            cpg_compute(y, state, t, out_state, cpg_out);
        }
    }
}

// Small GEMV (cols = 64): one warp per row.
__global__ void gemv_w64(const float* __restrict__ W, const float* __restrict__ b,
                         const float* __restrict__ x, float* __restrict__ y, int rows) {
    int row = (blockIdx.x * blockDim.x + threadIdx.x) >> 5;
    int lane = threadIdx.x & 31;
    if (row >= rows) return;
    const float* Wr = W + (size_t)row * 64;
    float sum = fmaf(Wr[lane], x[lane], Wr[32 + lane] * x[32 + lane]);
    sum = warp_reduce(sum);
    if (lane == 0) y[row] = fmaxf(sum + b[row], 0.0f);
}

// ---------------- host ----------------
extern "C" void kernel_launch(void* const* d_in, const int* in_sizes, int n_in,
                              void* d_out, int out_size) {
    const float* state = (const float*)d_in[0];
    const float* x     = (const float*)d_in[1];
    const float* t     = (const float*)d_in[2];
    const float* inW0  = (const float*)d_in[3];
    const float* inb0  = (const float*)d_in[4];
    const float* inW1  = (const float*)d_in[5];
    const float* inb1  = (const float*)d_in[6];
    const float* inW2  = (const float*)d_in[7];
    const float* inb2  = (const float*)d_in[8];
    const float* outW0 = (const float*)d_in[9];
    const float* outb0 = (const float*)d_in[10];
    const float* outW1 = (const float*)d_in[11];
    const float* outb1 = (const float*)d_in[12];
    const float* outW2 = (const float*)d_in[13];
    const float* outb2 = (const float*)d_in[14];
    float* out = (float*)d_out;

    float *h1, *h2, *params, *cpg, *h3, *h4;
    cudaGetSymbolAddress((void**)&h1, g_h1);
    cudaGetSymbolAddress((void**)&h2, g_h2);
    cudaGetSymbolAddress((void**)&params, g_params);
    cudaGetSymbolAddress((void**)&cpg, g_cpg);
    cudaGetSymbolAddress((void**)&h3, g_h3);
    cudaGetSymbolAddress((void**)&h4, g_h4);

    // input MLP; third layer fuses the CPG RK4 step into its last block
    gemv_in0<<<2048, 256>>>(inW0, inb0, x, t, h1);
    gemv4<4096, true, false><<<1024, 256>>>(inW1, inb1, h1, h2,
                                            nullptr, nullptr, nullptr, nullptr);
    gemv4<4096, false, true><<<528, 256>>>(inW2, inb2, h2, params,
                                           state, t, out, cpg);

    // output MLP
    gemv_w64<<<256, 256>>>(outW0, outb0, cpg, h3, 2048);
    gemv4<2048, true, false><<<512, 256>>>(outW1, outb1, h3, h4,
                                           nullptr, nullptr, nullptr, nullptr);
    gemv4<2048, false, false><<<256, 256>>>(outW2, outb2, h4, out + 96,
                                            nullptr, nullptr, nullptr, nullptr);
}

// round 6
// speedup vs baseline: 4.4875x; 1.0471x over previous
#include <cuda_runtime.h>
#include <cuda_bf16.h>
#include <math.h>

// ---------------- scratch (no cudaMalloc allowed) ----------------
__device__ __align__(16) float g_h1[4096];     // after in_W0
__device__ __align__(16) float g_h2[4096];     // after in_W1
__device__ __align__(16) float g_params[2112]; // after in_W2
__device__ __align__(16) float g_cpg[64];      // cpg_out
__device__ __align__(16) float g_h3[2048];     // after out_W0
__device__ __align__(16) float g_h4[2048];     // after out_W1
__device__ unsigned g_done = 0;                // last-block counter (self-resetting)

// ---------------- reductions ----------------
__device__ __forceinline__ float warp_reduce(float v) {
#pragma unroll
    for (int o = 16; o; o >>= 1) v += __shfl_down_sync(0xffffffffu, v, o);
    return v;
}

// ---------------- accurate sin: fp32 Cody-Waite 3-term + quadrant ----------
// Immune to --use_fast_math (hand-rolled). DP fallback for |x|>32768 (unused
// in practice). qoff=1 gives cos.
__device__ __forceinline__ float trig_acc(float x, int qoff) {
    float q, r;
    if (__builtin_expect(fabsf(x) > 32768.0f, 0)) {
        double xd = (double)x;
        double qd = rint(xd * 0.63661977236758138);
        q = (float)qd;
        r = (float)fma(qd, -1.5707963267948966, xd);
    } else {
        q = rintf(x * 0.63661977236758138f);
        r = fmaf(q, -1.5703125f, x);
        r = fmaf(q, -4.837512969970703125e-4f, r);
        r = fmaf(q, -7.549789948768648e-8f, r);
    }
    int n = ((int)q + qoff) & 3;
    float r2 = r * r;
    float ps = fmaf(r2, fmaf(r2, -1.9515295891e-4f, 8.3321608736e-3f), -1.6666654611e-1f);
    float s  = fmaf(r * r2, ps, r);
    float pc = fmaf(r2, fmaf(r2, -1.388731625493765e-3f, 4.166664568298827e-2f),
                    -4.999999905424326e-1f);
    float c  = fmaf(r2, pc, 1.0f);
    float v  = (n & 1) ? c : s;
    return (n & 2) ? -v : v;
}
__device__ __forceinline__ float sin_acc(float x) { return trig_acc(x, 0); }
__device__ __forceinline__ float cos_acc(float x) { return trig_acc(x, 1); }

// ---------------- L2 prefetch helper ----------------
__device__ __forceinline__ void l2_prefetch_region(const char* p, size_t bytes,
                                                   unsigned gid, unsigned gthreads) {
    size_t lines = bytes >> 7;
    for (size_t l = gid; l < lines; l += gthreads)
        asm volatile("prefetch.global.L2 [%0];" :: "l"(p + (l << 7)));
}

// ---------------- CPG RK4(3/8) device function (256 threads) ----------------
// i = tid&31 (oscillator), g = tid>>5 (8 groups x 4 coupling partners).
// ODE (reference slot permutation replicated exactly):
//   s0' = s1
//   s1' = ifr[i] + sum_j s0[i]*cw[i][j]*sin(s2[j]-s2[i]-pb[i][j])
//   s2' = 1000*(250*(ia[i]-s0[i]) - s1[i])
// Output: a = new[0:32], ph = new[32:64]; cpg_out = [a*cos(ph), a*sin(ph)]
// params read with __ldcg: written by OTHER blocks of this kernel (L2-coherent).
__device__ void cpg_compute(const float* params, const float* state,
                            const float* t_ptr, float* out_state, float* cpg_out) {
    const int tid = threadIdx.x;  // 0..255
    const int i   = tid & 31;
    const int g   = tid >> 5;     // 0..7

    __shared__ float sh_ph[2][32];
    __shared__ float sh_part[8][32];

    float cwv[4], pbv[4];
#pragma unroll
    for (int k = 0; k < 4; k++) {
        cwv[k] = __ldcg(params + 64 + 32 * i + 4 * g + k);
        pbv[k] = __ldcg(params + 64 + 1024 + 32 * i + 4 * g + k);
    }
    const float ia  = __ldcg(params + i);
    const float ifr = __ldcg(params + 32 + i);
    const float h   = *t_ptr;
    const float s0 = state[i], s1 = state[32 + i], s2 = state[64 + i];

    int stage = 0;
    auto f = [&](float a0, float a1, float a2, float& d0, float& d1, float& d2) {
        int buf = stage & 1;
        if (g == 0) sh_ph[buf][i] = a2;
        __syncthreads();
        const float* ph = sh_ph[buf] + 4 * g;
        float acc0, acc1;
        acc0 = cwv[0] * sin_acc(ph[0] - a2 - pbv[0]);
        acc1 = cwv[1] * sin_acc(ph[1] - a2 - pbv[1]);
        acc0 = fmaf(cwv[2], sin_acc(ph[2] - a2 - pbv[2]), acc0);
        acc1 = fmaf(cwv[3], sin_acc(ph[3] - a2 - pbv[3]), acc1);
        sh_part[g][i] = acc0 + acc1;
        __syncthreads();
        float coup = ((sh_part[0][i] + sh_part[1][i]) + (sh_part[2][i] + sh_part[3][i]))
                   + ((sh_part[4][i] + sh_part[5][i]) + (sh_part[6][i] + sh_part[7][i]));
        d1 = fmaf(a0, coup, ifr);
        d0 = a1;
        d2 = 1000.0f * fmaf(250.0f, ia - a0, -a1);
        stage++;
    };

    float k10, k11, k12, k20, k21, k22, k30, k31, k32, k40, k41, k42;
    f(s0, s1, s2, k10, k11, k12);
    f(s0 + h * k10 / 3.0f, s1 + h * k11 / 3.0f, s2 + h * k12 / 3.0f, k20, k21, k22);
    f(s0 + h * (k20 - k10 / 3.0f), s1 + h * (k21 - k11 / 3.0f), s2 + h * (k22 - k12 / 3.0f),
      k30, k31, k32);
    f(s0 + h * (k10 - k20 + k30), s1 + h * (k11 - k21 + k31), s2 + h * (k12 - k22 + k32),
      k40, k41, k42);

    float n0 = s0 + h * 0.125f * (k10 + 3.0f * (k20 + k30) + k40);
    float n1 = s1 + h * 0.125f * (k11 + 3.0f * (k21 + k31) + k41);
    float n2 = s2 + h * 0.125f * (k12 + 3.0f * (k22 + k32) + k42);

    if (g == 0) {
        out_state[i]      = n0;
        out_state[32 + i] = n1;
        out_state[64 + i] = n2;
        // a = n0, ph = n1 (reference reads ph from slot [n:2n])
        cpg_out[i]      = n0 * cos_acc(n1);
        cpg_out[32 + i] = n0 * sin_acc(n1);
    }
}

// ---------------- GEMV kernels ----------------
// Layer 0: rows=4096, cols=2049 (last col multiplies timestep). Scalar loads
// (row stride 2049 breaks float4 alignment on odd rows); 4 rows/block.
__global__ void gemv_in0(const float* __restrict__ W, const float* __restrict__ b,
                         const float* __restrict__ x, const float* __restrict__ t,
                         float* __restrict__ y) {
    int r0 = blockIdx.x * 4;
    const float* W0 = W + (size_t)r0 * 2049;
    const float* W1 = W0 + 2049;
    const float* W2 = W1 + 2049;
    const float* W3 = W2 + 2049;
    float s0 = 0.0f, s1 = 0.0f, s2 = 0.0f, s3 = 0.0f;
#pragma unroll
    for (int it = 0; it < 8; it++) {
        int j = threadIdx.x + it * 256;
        float xv = x[j];
        s0 = fmaf(__ldcs(W0 + j), xv, s0);
        s1 = fmaf(__ldcs(W1 + j), xv, s1);
        s2 = fmaf(__ldcs(W2 + j), xv, s2);
        s3 = fmaf(__ldcs(W3 + j), xv, s3);
    }
    if (threadIdx.x == 0) {
        float tv = *t;
        s0 = fmaf(__ldcs(W0 + 2048), tv, s0);
        s1 = fmaf(__ldcs(W1 + 2048), tv, s1);
        s2 = fmaf(__ldcs(W2 + 2048), tv, s2);
        s3 = fmaf(__ldcs(W3 + 2048), tv, s3);
    }
    __shared__ float sm[4][8];
    int lane = threadIdx.x & 31, w = threadIdx.x >> 5;
    s0 = warp_reduce(s0); s1 = warp_reduce(s1);
    s2 = warp_reduce(s2); s3 = warp_reduce(s3);
    if (lane == 0) { sm[0][w] = s0; sm[1][w] = s1; sm[2][w] = s2; sm[3][w] = s3; }
    __syncthreads();
    if (w == 0) {
        int rr = lane >> 3, sl = lane & 7;
        float v = sm[rr][sl];
        v += __shfl_down_sync(0xffffffffu, v, 4);
        v += __shfl_down_sync(0xffffffffu, v, 2);
        v += __shfl_down_sync(0xffffffffu, v, 1);
        if (sl == 0) y[r0 + rr] = fmaxf(v + b[r0 + rr], 0.0f);
    }
}

// float4 GEMV, 4 rows per 256-thread block, COLS % 1024 == 0.
// FUSE_CPG: after all blocks finish, the last block runs the CPG step inline
// while the other blocks prefetch the output-MLP weights into L2.
template<int COLS, bool RELU, bool FUSE_CPG>
__global__ void gemv4(const float* __restrict__ W, const float* __restrict__ b,
                      const float* __restrict__ x, float* __restrict__ y,
                      const float* state, const float* t,
                      float* out_state, float* cpg_out,
                      const float* pf0, const float* pf1, const float* pf2) {
    constexpr int N4 = COLS / 4;
    constexpr int ITERS = N4 / 256;
    int r0 = blockIdx.x * 4;
    const float4* W0 = (const float4*)(W + (size_t)r0 * COLS);
    const float4* W1 = (const float4*)(W + (size_t)(r0 + 1) * COLS);
    const float4* W2 = (const float4*)(W + (size_t)(r0 + 2) * COLS);
    const float4* W3 = (const float4*)(W + (size_t)(r0 + 3) * COLS);
    const float4* x4 = (const float4*)x;
    float s0 = 0.0f, s1 = 0.0f, s2 = 0.0f, s3 = 0.0f;
#pragma unroll
    for (int it = 0; it < ITERS; it++) {
        int j = threadIdx.x + it * 256;
        float4 v  = x4[j];
        float4 w0 = __ldcs(W0 + j);
        float4 w1 = __ldcs(W1 + j);
        float4 w2 = __ldcs(W2 + j);
        float4 w3 = __ldcs(W3 + j);
        s0 += w0.x * v.x + w0.y * v.y + w0.z * v.z + w0.w * v.w;
        s1 += w1.x * v.x + w1.y * v.y + w1.z * v.z + w1.w * v.w;
        s2 += w2.x * v.x + w2.y * v.y + w2.z * v.z + w2.w * v.w;
        s3 += w3.x * v.x + w3.y * v.y + w3.z * v.z + w3.w * v.w;
    }
    __shared__ float sm[4][8];
    int lane = threadIdx.x & 31, w = threadIdx.x >> 5;
    s0 = warp_reduce(s0); s1 = warp_reduce(s1);
    s2 = warp_reduce(s2); s3 = warp_reduce(s3);
    if (lane == 0) { sm[0][w] = s0; sm[1][w] = s1; sm[2][w] = s2; sm[3][w] = s3; }
    __syncthreads();
    if (w == 0) {
        int rr = lane >> 3, sl = lane & 7;
        float v = sm[rr][sl];
        v += __shfl_down_sync(0xffffffffu, v, 4);
        v += __shfl_down_sync(0xffffffffu, v, 2);
        v += __shfl_down_sync(0xffffffffu, v, 1);
        if (sl == 0) {
            float r = v + b[r0 + rr];
            y[r0 + rr] = RELU ? fmaxf(r, 0.0f) : r;
        }
    }

    if (FUSE_CPG) {
        // last-block election: writers fence, then RMW on a shared counter
        __shared__ unsigned sh_last;
        __syncthreads();
        if (threadIdx.x == 0) {
            __threadfence();
            sh_last = (atomicAdd(&g_done, 1u) == gridDim.x - 1u) ? 1u : 0u;
        }
        __syncthreads();
        if (sh_last) {
            if (threadIdx.x == 0) g_done = 0; // reset for next graph replay
            cpg_compute(y, state, t, out_state, cpg_out);
        } else {
            // prefetch the output MLP's weights into L2 during the cpg stall
            unsigned gid = blockIdx.x * 256u + threadIdx.x;
            unsigned gth = gridDim.x * 256u;
            l2_prefetch_region((const char*)pf0, 2048u * 64u * 4u, gid, gth);
            l2_prefetch_region((const char*)pf1, 2048u * 2048u * 4u, gid, gth);
            l2_prefetch_region((const char*)pf2, 1024u * 2048u * 4u, gid, gth);
        }
    }
}

// Small GEMV (cols = 64): 2 rows per warp, 8 warps/block.
__global__ void gemv_w64(const float* __restrict__ W, const float* __restrict__ b,
                         const float* __restrict__ x, float* __restrict__ y) {
    int warp_id = (blockIdx.x * blockDim.x + threadIdx.x) >> 5;
    int lane = threadIdx.x & 31;
    int r0 = warp_id * 2;
    const float* W0 = W + (size_t)r0 * 64;
    const float* W1 = W0 + 64;
    float x0 = x[lane], x1 = x[32 + lane];
    float s0 = fmaf(W0[lane], x0, W0[32 + lane] * x1);
    float s1 = fmaf(W1[lane], x0, W1[32 + lane] * x1);
    s0 = warp_reduce(s0);
    s1 = warp_reduce(s1);
    if (lane == 0) {
        y[r0]     = fmaxf(s0 + b[r0], 0.0f);
        y[r0 + 1] = fmaxf(s1 + b[r0 + 1], 0.0f);
    }
}

// ---------------- host ----------------
extern "C" void kernel_launch(void* const* d_in, const int* in_sizes, int n_in,
                              void* d_out, int out_size) {
    const float* state = (const float*)d_in[0];
    const float* x     = (const float*)d_in[1];
    const float* t     = (const float*)d_in[2];
    const float* inW0  = (const float*)d_in[3];
    const float* inb0  = (const float*)d_in[4];
    const float* inW1  = (const float*)d_in[5];
    const float* inb1  = (const float*)d_in[6];
    const float* inW2  = (const float*)d_in[7];
    const float* inb2  = (const float*)d_in[8];
    const float* outW0 = (const float*)d_in[9];
    const float* outb0 = (const float*)d_in[10];
    const float* outW1 = (const float*)d_in[11];
    const float* outb1 = (const float*)d_in[12];
    const float* outW2 = (const float*)d_in[13];
    const float* outb2 = (const float*)d_in[14];
    float* out = (float*)d_out;

    float *h1, *h2, *params, *cpg, *h3, *h4;
    cudaGetSymbolAddress((void**)&h1, g_h1);
    cudaGetSymbolAddress((void**)&h2, g_h2);
    cudaGetSymbolAddress((void**)&params, g_params);
    cudaGetSymbolAddress((void**)&cpg, g_cpg);
    cudaGetSymbolAddress((void**)&h3, g_h3);
    cudaGetSymbolAddress((void**)&h4, g_h4);

    // input MLP; third layer fuses the CPG RK4 step + out-MLP L2 prefetch
    gemv_in0<<<1024, 256>>>(inW0, inb0, x, t, h1);
    gemv4<4096, true, false><<<1024, 256>>>(inW1, inb1, h1, h2,
                                            nullptr, nullptr, nullptr, nullptr,
                                            nullptr, nullptr, nullptr);
    gemv4<4096, false, true><<<528, 256>>>(inW2, inb2, h2, params,
                                           state, t, out, cpg,
                                           outW0, outW1, outW2);

    // output MLP
    gemv_w64<<<128, 256>>>(outW0, outb0, cpg, h3);
    gemv4<2048, true, false><<<512, 256>>>(outW1, outb1, h3, h4,
                                           nullptr, nullptr, nullptr, nullptr,
                                           nullptr, nullptr, nullptr);
    gemv4<2048, false, false><<<256, 256>>>(outW2, outb2, h4, out + 96,
                                            nullptr, nullptr, nullptr, nullptr,
                                            nullptr, nullptr, nullptr);
}